// round 11
// baseline (speedup 1.0000x reference)
#include <cuda_runtime.h>
#include <cuda_bf16.h>
#include <math.h>

#define BATCH 8
#define PP 256
#define NN 4096
#define CC 512
#define EPSV 1e-5f
#define SMP 136   // smem row stride (words): 136 mod 32 == 8 -> conflict-free frag loads

// ---------------- scratch ------------------------------------------------------
__device__ unsigned g_Xh[BATCH*CC*NN/2];  // x as bf16 hi, packed 2/uint
__device__ unsigned g_Xl[BATCH*CC*NN/2];  // x residual lo
__device__ float g_G [BATCH*CC*CC];   // X X^T per batch
__device__ float g_T [BATCH*PP*CC];   // wq @ G
__device__ float g_A [BATCH*PP*PP];   // softmax(attention)
__device__ float g_M [BATCH*PP*PP];   // Wc @ A^T
__device__ float g_Wc[PP*PP];
__device__ float g_WX[PP*CC];
__device__ float g_ctot[PP];
__device__ float g_sx[BATCH*CC];
__device__ float g_u [BATCH*PP];
__device__ float g_vv[BATCH*PP];
__device__ float g_s1[PP], g_t1[PP], g_so[PP], g_to[PP];
__device__ float g_sx1[PP], g_tx1[PP], g_sx2[PP], g_tx2[PP];

// ---------------- mma helpers --------------------------------------------------
__device__ __forceinline__ unsigned f2tf(float f) {
    unsigned u;
    asm("cvt.rna.tf32.f32 %0, %1;" : "=r"(u) : "f"(f));
    return u;
}
__device__ __forceinline__ void mma8(float c[4], const unsigned a[4], const unsigned b[2]) {
    asm volatile(
        "mma.sync.aligned.m16n8k8.row.col.f32.tf32.tf32.f32 "
        "{%0,%1,%2,%3},{%4,%5,%6,%7},{%8,%9},{%0,%1,%2,%3};\n"
        : "+f"(c[0]), "+f"(c[1]), "+f"(c[2]), "+f"(c[3])
        : "r"(a[0]), "r"(a[1]), "r"(a[2]), "r"(a[3]), "r"(b[0]), "r"(b[1]));
}
__device__ __forceinline__ void mmabf(float c[4], const unsigned a[4], const unsigned b[2]) {
    asm volatile(
        "mma.sync.aligned.m16n8k16.row.col.f32.bf16.bf16.f32 "
        "{%0,%1,%2,%3},{%4,%5,%6,%7},{%8,%9},{%0,%1,%2,%3};\n"
        : "+f"(c[0]), "+f"(c[1]), "+f"(c[2]), "+f"(c[3])
        : "r"(a[0]), "r"(a[1]), "r"(a[2]), "r"(a[3]), "r"(b[0]), "r"(b[1]));
}
__device__ __forceinline__ void pack2(float a, float b, unsigned& h, unsigned& l) {
    __nv_bfloat16 ha = __float2bfloat16(a), hb = __float2bfloat16(b);
    __nv_bfloat16 la = __float2bfloat16(a - __bfloat162float(ha));
    __nv_bfloat16 lb = __float2bfloat16(b - __bfloat162float(hb));
    h = ((unsigned)__bfloat16_as_ushort(hb) << 16) | __bfloat16_as_ushort(ha);
    l = ((unsigned)__bfloat16_as_ushort(lb) << 16) | __bfloat16_as_ushort(la);
}

// ---------------- BN fold ------------------------------------------------------
__global__ void fold_vectors(
    const float* __restrict__ g1,  const float* __restrict__ b1,
    const float* __restrict__ m1,  const float* __restrict__ v1,
    const float* __restrict__ go,  const float* __restrict__ bo_,
    const float* __restrict__ mo,  const float* __restrict__ vo,
    const float* __restrict__ gx1, const float* __restrict__ bx1_,
    const float* __restrict__ mx1, const float* __restrict__ vx1,
    const float* __restrict__ gx2, const float* __restrict__ bx2_,
    const float* __restrict__ mx2, const float* __restrict__ vx2)
{
    int p = threadIdx.x;
    float s;
    s = g1 [p]*rsqrtf(v1 [p]+EPSV); g_s1 [p]=s; g_t1 [p]=b1 [p]-m1 [p]*s;
    s = go [p]*rsqrtf(vo [p]+EPSV); g_so [p]=s; g_to [p]=bo_[p]-mo [p]*s;
    s = gx1[p]*rsqrtf(vx1[p]+EPSV); g_sx1[p]=s; g_tx1[p]=bx1_[p]-mx1[p]*s;
    s = gx2[p]*rsqrtf(vx2[p]+EPSV); g_sx2[p]=s; g_tx2[p]=bx2_[p]-mx2[p]*s;
}

// ---------------- combine linear chains ---------------------------------------
__global__ void combine_w(
    const float* __restrict__ wo,  const float* __restrict__ bo,
    const float* __restrict__ w1d,
    const float* __restrict__ wx2, const float* __restrict__ bx2,
    const float* __restrict__ wx1, const float* __restrict__ bx1)
{
    int o = blockIdx.x;
    int t = threadIdx.x;
    __shared__ float a1[PP], a2[PP], red[PP];
    float wo_k  = wo [o*PP + t];
    float wx2_k = wx2[o*PP + t];
    float so  = g_so[o], sx2 = g_sx2[o];
    a1[t] = wo_k  * g_s1 [t];
    a2[t] = wx2_k * g_sx1[t];
    red[t] = so * wo_k * g_t1[t]
           + sx2 * wx2_k * (g_sx1[t]*bx1[t] + g_tx1[t]);
    __syncthreads();
    for (int s = 128; s > 0; s >>= 1) {
        if (t < s) red[t] += red[t + s];
        __syncthreads();
    }
    if (t == 0)
        g_ctot[o] = red[0] + so*bo[o] + g_to[o] + sx2*bx2[o] + g_tx2[o];

    float s1sum = 0.f;
    #pragma unroll 8
    for (int k = 0; k < PP; k++) s1sum += a1[k] * w1d[k*PP + t];
    g_Wc[o*PP + t] = so * s1sum;

    float sA = 0.f, sB = 0.f;
    #pragma unroll 8
    for (int k = 0; k < PP; k++) {
        float w = a2[k];
        sA += w * wx1[k*CC + t];
        sB += w * wx1[k*CC + t + 256];
    }
    g_WX[o*CC + t]       = sx2 * sA;
    g_WX[o*CC + t + 256] = sx2 * sB;
}

// ---------------- fused: x -> bf16 hi/lo + row sums ----------------------------
__global__ __launch_bounds__(256) void convsx(const float* __restrict__ x)
{
    int row = blockIdx.x;                 // b*CC + c
    const float* src = x + (size_t)row*NN;
    unsigned* dh = g_Xh + (size_t)row*(NN/2);
    unsigned* dl = g_Xl + (size_t)row*(NN/2);
    int t = threadIdx.x;
    float s = 0.f;
    #pragma unroll
    for (int i = 0; i < 4; i++) {
        int e = t*4 + i*1024;             // coalesced float4
        float4 v = *(const float4*)&src[e];
        s += v.x + v.y + v.z + v.w;
        unsigned h01, l01, h23, l23;
        pack2(v.x, v.y, h01, l01);
        pack2(v.z, v.w, h23, l23);
        *(uint2*)&dh[e>>1] = make_uint2(h01, h23);
        *(uint2*)&dl[e>>1] = make_uint2(l01, l23);
    }
    __shared__ float wsum[8];
    #pragma unroll
    for (int o = 16; o > 0; o >>= 1) s += __shfl_xor_sync(0xffffffffu, s, o);
    if ((t & 31) == 0) wsum[t >> 5] = s;
    __syncthreads();
    if (t < 8) {
        float v = wsum[t];
        #pragma unroll
        for (int o = 4; o > 0; o >>= 1) v += __shfl_xor_sync(0xffu, v, o);
        if (t == 0) g_sx[row] = v;
    }
}

// ---------------- u = wq@sx, vv = wv@sx ----------------------------------------
__global__ void uv_k(const float* __restrict__ wq, const float* __restrict__ wv)
{
    int b = blockIdx.y;
    int w = threadIdx.x >> 5, lane = threadIdx.x & 31;
    int p = blockIdx.x * 8 + w;
    const float* sx = g_sx + b*CC;
    float su = 0.f, sv = 0.f;
    #pragma unroll
    for (int it = 0; it < 4; it++) {
        int c = lane*4 + it*128;
        float4 s4 = *(const float4*)&sx[c];
        float4 q4 = *(const float4*)&wq[p*CC + c];
        float4 v4 = *(const float4*)&wv[p*CC + c];
        su += q4.x*s4.x + q4.y*s4.y + q4.z*s4.z + q4.w*s4.w;
        sv += v4.x*s4.x + v4.y*s4.y + v4.z*s4.z + v4.w*s4.w;
    }
    #pragma unroll
    for (int o = 16; o > 0; o >>= 1) {
        su += __shfl_xor_sync(0xffffffffu, su, o);
        sv += __shfl_xor_sync(0xffffffffu, sv, o);
    }
    if (lane == 0) { g_u[b*PP + p] = su; g_vv[b*PP + p] = sv; }
}

// ---------------- G = X X^T  (bf16 2-split, 128x128, double-buffered) ----------
__global__ __launch_bounds__(256) void gemm_G()
{
    int batch = blockIdx.z;
    const unsigned* Xh = g_Xh + ((size_t)batch*CC*NN >> 1);
    const unsigned* Xl = g_Xl + ((size_t)batch*CC*NN >> 1);
    float* G = g_G + (size_t)batch*CC*CC;
    int m0 = blockIdx.y*128, n0 = blockIdx.x*128;
    __shared__ unsigned Ah_s[16][SMP], Al_s[16][SMP], Bh_s[16][SMP], Bl_s[16][SMP];
    int tid = threadIdx.x, lane = tid & 31, wid = tid >> 5;
    int wm = (wid & 1)*64, wn = (wid >> 1)*32;
    float c[4][4][4];
    #pragma unroll
    for (int i = 0; i < 4; i++) {
        #pragma unroll
        for (int j = 0; j < 4; j++) { c[i][j][0]=0.f; c[i][j][1]=0.f; c[i][j][2]=0.f; c[i][j][3]=0.f; }
    }

    int lr = tid >> 1, lc = (tid & 1)*8;
    const int NW = NN >> 1;
    const unsigned* pAh = &Xh[(size_t)(m0+lr)*NW + lc];
    const unsigned* pAl = &Xl[(size_t)(m0+lr)*NW + lc];
    const unsigned* pBh = &Xh[(size_t)(n0+lr)*NW + lc];
    const unsigned* pBl = &Xl[(size_t)(n0+lr)*NW + lc];

    uint4 ah0 = *(const uint4*)pAh, ah1 = *(const uint4*)(pAh+4);
    uint4 al0 = *(const uint4*)pAl, al1 = *(const uint4*)(pAl+4);
    uint4 bh0 = *(const uint4*)pBh, bh1 = *(const uint4*)(pBh+4);
    uint4 bl0 = *(const uint4*)pBl, bl1 = *(const uint4*)(pBl+4);

    for (int kp0 = 0; kp0 < NW; kp0 += 16) {
        Ah_s[lc+0][lr]=ah0.x; Ah_s[lc+1][lr]=ah0.y; Ah_s[lc+2][lr]=ah0.z; Ah_s[lc+3][lr]=ah0.w;
        Ah_s[lc+4][lr]=ah1.x; Ah_s[lc+5][lr]=ah1.y; Ah_s[lc+6][lr]=ah1.z; Ah_s[lc+7][lr]=ah1.w;
        Al_s[lc+0][lr]=al0.x; Al_s[lc+1][lr]=al0.y; Al_s[lc+2][lr]=al0.z; Al_s[lc+3][lr]=al0.w;
        Al_s[lc+4][lr]=al1.x; Al_s[lc+5][lr]=al1.y; Al_s[lc+6][lr]=al1.z; Al_s[lc+7][lr]=al1.w;
        Bh_s[lc+0][lr]=bh0.x; Bh_s[lc+1][lr]=bh0.y; Bh_s[lc+2][lr]=bh0.z; Bh_s[lc+3][lr]=bh0.w;
        Bh_s[lc+4][lr]=bh1.x; Bh_s[lc+5][lr]=bh1.y; Bh_s[lc+6][lr]=bh1.z; Bh_s[lc+7][lr]=bh1.w;
        Bl_s[lc+0][lr]=bl0.x; Bl_s[lc+1][lr]=bl0.y; Bl_s[lc+2][lr]=bl0.z; Bl_s[lc+3][lr]=bl0.w;
        Bl_s[lc+4][lr]=bl1.x; Bl_s[lc+5][lr]=bl1.y; Bl_s[lc+6][lr]=bl1.z; Bl_s[lc+7][lr]=bl1.w;
        __syncthreads();
        if (kp0 + 16 < NW) {
            ah0 = *(const uint4*)(pAh + kp0+16); ah1 = *(const uint4*)(pAh + kp0+20);
            al0 = *(const uint4*)(pAl + kp0+16); al1 = *(const uint4*)(pAl + kp0+20);
            bh0 = *(const uint4*)(pBh + kp0+16); bh1 = *(const uint4*)(pBh + kp0+20);
            bl0 = *(const uint4*)(pBl + kp0+16); bl1 = *(const uint4*)(pBl + kp0+20);
        }
        #pragma unroll
        for (int kk = 0; kk < 16; kk += 8) {
            unsigned ah[4][4], al[4][4], bh[4][2], bl[4][2];
            int kb = kk + (lane & 3);
            int mb = wm + (lane >> 2);
            #pragma unroll
            for (int im = 0; im < 4; im++) {
                int m = mb + im*16;
                ah[im][0]=Ah_s[kb][m];   ah[im][1]=Ah_s[kb][m+8];
                ah[im][2]=Ah_s[kb+4][m]; ah[im][3]=Ah_s[kb+4][m+8];
                al[im][0]=Al_s[kb][m];   al[im][1]=Al_s[kb][m+8];
                al[im][2]=Al_s[kb+4][m]; al[im][3]=Al_s[kb+4][m+8];
            }
            int nb = wn + (lane >> 2);
            #pragma unroll
            for (int jn = 0; jn < 4; jn++) {
                int n = nb + jn*8;
                bh[jn][0]=Bh_s[kb][n]; bh[jn][1]=Bh_s[kb+4][n];
                bl[jn][0]=Bl_s[kb][n]; bl[jn][1]=Bl_s[kb+4][n];
            }
            #pragma unroll
            for (int im = 0; im < 4; im++) {
                #pragma unroll
                for (int jn = 0; jn < 4; jn++) {
                    mmabf(c[im][jn], ah[im], bh[jn]);
                    mmabf(c[im][jn], al[im], bh[jn]);
                    mmabf(c[im][jn], ah[im], bl[jn]);
                }
            }
        }
        __syncthreads();
    }
    #pragma unroll
    for (int im = 0; im < 4; im++) {
        int r0 = m0 + wm + im*16 + (lane >> 2);
        #pragma unroll
        for (int jn = 0; jn < 4; jn++) {
            int col = n0 + wn + jn*8 + 2*(lane & 3);
            *(float2*)&G[(size_t)r0*CC + col]     = make_float2(c[im][jn][0], c[im][jn][1]);
            *(float2*)&G[(size_t)(r0+8)*CC + col] = make_float2(c[im][jn][2], c[im][jn][3]);
        }
    }
}

// ---------------- T = wq @ G  (fp32 SIMT, 64x128 tile, dbuf) -------------------
__global__ __launch_bounds__(256) void gemm_T(const float* __restrict__ wq)
{
    int batch = blockIdx.z;
    const float* Gm = g_G + (size_t)batch*CC*CC;
    float* Out = g_T + (size_t)batch*PP*CC;
    int m0 = blockIdx.y*64, n0 = blockIdx.x*128;
    __shared__ float Ws[16][65];
    __shared__ float Xs[16][128];
    int tid = threadIdx.x;
    int tm4 = (tid >> 4) * 4;
    int tn4 = (tid & 15) * 4;
    float acc[4][8];
    #pragma unroll
    for (int i = 0; i < 4; i++) {
        #pragma unroll
        for (int j = 0; j < 8; j++) acc[i][j] = 0.f;
    }
    int wr = tid >> 2, wc4 = (tid & 3) * 4;
    int xr = tid >> 4, xc = tid & 15;

    float4 w4 = *(const float4*)&wq[(m0+wr)*CC + wc4];
    const float4* Xr0 = (const float4*)&Gm[(size_t)xr*CC + n0];
    float4 x0 = Xr0[xc], x1 = Xr0[xc+16];

    for (int k0 = 0; k0 < CC; k0 += 16) {
        Ws[wc4+0][wr]=w4.x; Ws[wc4+1][wr]=w4.y; Ws[wc4+2][wr]=w4.z; Ws[wc4+3][wr]=w4.w;
        *(float4*)&Xs[xr][xc*4]    = x0;
        *(float4*)&Xs[xr][64+xc*4] = x1;
        __syncthreads();
        if (k0 + 16 < CC) {
            w4 = *(const float4*)&wq[(m0+wr)*CC + k0+16 + wc4];
            const float4* Xr = (const float4*)&Gm[(size_t)(k0+16+xr)*CC + n0];
            x0 = Xr[xc]; x1 = Xr[xc+16];
        }
        #pragma unroll
        for (int k = 0; k < 16; k++) {
            float a0=Ws[k][tm4+0], a1=Ws[k][tm4+1], a2=Ws[k][tm4+2], a3=Ws[k][tm4+3];
            float4 b0 = *(const float4*)&Xs[k][tn4];
            float4 b1 = *(const float4*)&Xs[k][tn4+64];
            acc[0][0]+=a0*b0.x; acc[0][1]+=a0*b0.y; acc[0][2]+=a0*b0.z; acc[0][3]+=a0*b0.w;
            acc[0][4]+=a0*b1.x; acc[0][5]+=a0*b1.y; acc[0][6]+=a0*b1.z; acc[0][7]+=a0*b1.w;
            acc[1][0]+=a1*b0.x; acc[1][1]+=a1*b0.y; acc[1][2]+=a1*b0.z; acc[1][3]+=a1*b0.w;
            acc[1][4]+=a1*b1.x; acc[1][5]+=a1*b1.y; acc[1][6]+=a1*b1.z; acc[1][7]+=a1*b1.w;
            acc[2][0]+=a2*b0.x; acc[2][1]+=a2*b0.y; acc[2][2]+=a2*b0.z; acc[2][3]+=a2*b0.w;
            acc[2][4]+=a2*b1.x; acc[2][5]+=a2*b1.y; acc[2][6]+=a2*b1.z; acc[2][7]+=a2*b1.w;
            acc[3][0]+=a3*b0.x; acc[3][1]+=a3*b0.y; acc[3][2]+=a3*b0.z; acc[3][3]+=a3*b0.w;
            acc[3][4]+=a3*b1.x; acc[3][5]+=a3*b1.y; acc[3][6]+=a3*b1.z; acc[3][7]+=a3*b1.w;
        }
        __syncthreads();
    }
    #pragma unroll
    for (int i = 0; i < 4; i++) {
        int row = m0 + tm4 + i;
        *(float4*)&Out[(size_t)row*CC + n0 + tn4]      = make_float4(acc[i][0],acc[i][1],acc[i][2],acc[i][3]);
        *(float4*)&Out[(size_t)row*CC + n0 + 64 + tn4] = make_float4(acc[i][4],acc[i][5],acc[i][6],acc[i][7]);
    }
}

// ---------------- fused S + rank-1 + softmax -> A  (16 rows x 256 cols) --------
__global__ __launch_bounds__(256) void gemm_SA(const float* __restrict__ wv,
                                               const float* __restrict__ bq,
                                               const float* __restrict__ bv)
{
    int batch = blockIdx.y;
    int p0 = blockIdx.x * 16;
    const float* T = g_T + (size_t)batch*PP*CC;
    float* A = g_A + (size_t)batch*PP*PP;
    __shared__ float Qs[32][17];    // [k][p] 16 rows
    __shared__ float Vs[32][264];   // [k][q] 256 cols
    int tid = threadIdx.x, wid = tid >> 5, lane = tid & 31;
    float acc[2][8];
    #pragma unroll
    for (int i = 0; i < 2; i++) {
        #pragma unroll
        for (int j = 0; j < 8; j++) acc[i][j] = 0.f;
    }

    for (int k0 = 0; k0 < CC; k0 += 32) {
        if (tid < 128) {
            int r = tid >> 3, c4 = (tid & 7) * 4;
            float4 q4 = *(const float4*)&T[(size_t)(p0+r)*CC + k0 + c4];
            Qs[c4+0][r]=q4.x; Qs[c4+1][r]=q4.y; Qs[c4+2][r]=q4.z; Qs[c4+3][r]=q4.w;
        }
        {
            int q = tid;
            const float4* wr = (const float4*)&wv[(size_t)q*CC + k0];
            #pragma unroll
            for (int j = 0; j < 8; j++) {
                float4 v = wr[j];
                Vs[j*4+0][q]=v.x; Vs[j*4+1][q]=v.y; Vs[j*4+2][q]=v.z; Vs[j*4+3][q]=v.w;
            }
        }
        __syncthreads();
        #pragma unroll
        for (int k = 0; k < 32; k++) {
            float a0 = Qs[k][wid*2], a1 = Qs[k][wid*2+1];
            float4 b0 = *(const float4*)&Vs[k][lane*8];
            float4 b1 = *(const float4*)&Vs[k][lane*8+4];
            acc[0][0]+=a0*b0.x; acc[0][1]+=a0*b0.y; acc[0][2]+=a0*b0.z; acc[0][3]+=a0*b0.w;
            acc[0][4]+=a0*b1.x; acc[0][5]+=a0*b1.y; acc[0][6]+=a0*b1.z; acc[0][7]+=a0*b1.w;
            acc[1][0]+=a1*b0.x; acc[1][1]+=a1*b0.y; acc[1][2]+=a1*b0.z; acc[1][3]+=a1*b0.w;
            acc[1][4]+=a1*b1.x; acc[1][5]+=a1*b1.y; acc[1][6]+=a1*b1.z; acc[1][7]+=a1*b1.w;
        }
        __syncthreads();
    }

    const float* u  = g_u  + batch*PP;
    const float* vv = g_vv + batch*PP;
    float4 bv0 = *(const float4*)&bv[lane*8];
    float4 bv1 = *(const float4*)&bv[lane*8+4];
    float4 vv0 = *(const float4*)&vv[lane*8];
    float4 vv1 = *(const float4*)&vv[lane*8+4];
    float e0[4] = {vv0.x + 4096.f*bv0.x, vv0.y + 4096.f*bv0.y,
                   vv0.z + 4096.f*bv0.z, vv0.w + 4096.f*bv0.w};
    float e1[4] = {vv1.x + 4096.f*bv1.x, vv1.y + 4096.f*bv1.y,
                   vv1.z + 4096.f*bv1.z, vv1.w + 4096.f*bv1.w};
    float bvv[8] = {bv0.x,bv0.y,bv0.z,bv0.w,bv1.x,bv1.y,bv1.z,bv1.w};
    float evv[8] = {e0[0],e0[1],e0[2],e0[3],e1[0],e1[1],e1[2],e1[3]};

    #pragma unroll
    for (int i = 0; i < 2; i++) {
        int p = p0 + wid*2 + i;
        float up = u[p], bqp = bq[p];
        float o[8], mx = -1e30f;
        #pragma unroll
        for (int j = 0; j < 8; j++) {
            o[j] = acc[i][j] + up*bvv[j] + bqp*evv[j];
            mx = fmaxf(mx, o[j]);
        }
        #pragma unroll
        for (int s = 16; s > 0; s >>= 1) mx = fmaxf(mx, __shfl_xor_sync(0xffffffffu, mx, s));
        float sum = 0.f;
        #pragma unroll
        for (int j = 0; j < 8; j++) { o[j] = __expf(o[j] - mx); sum += o[j]; }
        #pragma unroll
        for (int s = 16; s > 0; s >>= 1) sum += __shfl_xor_sync(0xffffffffu, sum, s);
        float inv = 1.f / sum;
        *(float4*)&A[(size_t)p*PP + lane*8]     = make_float4(o[0]*inv, o[1]*inv, o[2]*inv, o[3]*inv);
        *(float4*)&A[(size_t)p*PP + lane*8 + 4] = make_float4(o[4]*inv, o[5]*inv, o[6]*inv, o[7]*inv);
    }
}

// ---------------- M = Wc @ A^T  (fp32 NT SIMT, 64x64 tiles, dbuf) --------------
__global__ __launch_bounds__(256) void gemm_M()
{
    int batch = blockIdx.z;
    const float* A = g_A + (size_t)batch*PP*PP;
    float* M = g_M + (size_t)batch*PP*PP;
    int o0 = blockIdx.y*64, p0 = blockIdx.x*64;

    __shared__ float Qs[32][65];   // Wc[k][o]
    __shared__ float Vs[32][65];   // A [k][p]
    int tid = threadIdx.x;
    int tm4 = (tid >> 4) * 4;
    int tn4 = (tid & 15) * 4;
    float acc[4][4];
    #pragma unroll
    for (int i = 0; i < 4; i++) {
        #pragma unroll
        for (int j = 0; j < 4; j++) acc[i][j] = 0.f;
    }
    int r = tid >> 2, c8 = (tid & 3) * 8;

    float4 qa = *(const float4*)&g_Wc[(o0+r)*PP + c8];
    float4 qb = *(const float4*)&g_Wc[(o0+r)*PP + c8 + 4];
    float4 va = *(const float4*)&A[(size_t)(p0+r)*PP + c8];
    float4 vb = *(const float4*)&A[(size_t)(p0+r)*PP + c8 + 4];

    for (int k0 = 0; k0 < PP; k0 += 32) {
        Qs[c8+0][r]=qa.x; Qs[c8+1][r]=qa.y; Qs[c8+2][r]=qa.z; Qs[c8+3][r]=qa.w;
        Qs[c8+4][r]=qb.x; Qs[c8+5][r]=qb.y; Qs[c8+6][r]=qb.z; Qs[c8+7][r]=qb.w;
        Vs[c8+0][r]=va.x; Vs[c8+1][r]=va.y; Vs[c8+2][r]=va.z; Vs[c8+3][r]=va.w;
        Vs[c8+4][r]=vb.x; Vs[c8+5][r]=vb.y; Vs[c8+6][r]=vb.z; Vs[c8+7][r]=vb.w;
        __syncthreads();
        if (k0 + 32 < PP) {
            qa = *(const float4*)&g_Wc[(o0+r)*PP + k0+32 + c8];
            qb = *(const float4*)&g_Wc[(o0+r)*PP + k0+32 + c8 + 4];
            va = *(const float4*)&A[(size_t)(p0+r)*PP + k0+32 + c8];
            vb = *(const float4*)&A[(size_t)(p0+r)*PP + k0+32 + c8 + 4];
        }
        #pragma unroll
        for (int k = 0; k < 32; k++) {
            float a0=Qs[k][tm4+0], a1=Qs[k][tm4+1], a2=Qs[k][tm4+2], a3=Qs[k][tm4+3];
            float b0=Vs[k][tn4+0], b1=Vs[k][tn4+1], b2=Vs[k][tn4+2], b3=Vs[k][tn4+3];
            acc[0][0]+=a0*b0; acc[0][1]+=a0*b1; acc[0][2]+=a0*b2; acc[0][3]+=a0*b3;
            acc[1][0]+=a1*b0; acc[1][1]+=a1*b1; acc[1][2]+=a1*b2; acc[1][3]+=a1*b3;
            acc[2][0]+=a2*b0; acc[2][1]+=a2*b1; acc[2][2]+=a2*b2; acc[2][3]+=a2*b3;
            acc[3][0]+=a3*b0; acc[3][1]+=a3*b1; acc[3][2]+=a3*b2; acc[3][3]+=a3*b3;
        }
        __syncthreads();
    }
    #pragma unroll
    for (int i = 0; i < 4; i++) {
        *(float4*)&M[(o0+tm4+i)*PP + p0 + tn4] =
            make_float4(acc[i][0], acc[i][1], acc[i][2], acc[i][3]);
    }
}

// ---------------- final: out = relu(M@Y + WX@x + ctot) (1x tf32, dbuf) ---------
__global__ __launch_bounds__(256) void gemm_final(const float* __restrict__ x,
                                                  const float* __restrict__ y,
                                                  float* __restrict__ out)
{
    int batch = blockIdx.z;
    const float* Mb = g_M + (size_t)batch*PP*PP;
    const float* Y  = y + (size_t)batch*PP*NN;
    const float* X  = x + (size_t)batch*CC*NN;
    float* Out = out + (size_t)batch*PP*NN;
    int m0 = blockIdx.y*128, n0 = blockIdx.x*128;
    __shared__ unsigned As[16][SMP], Bs[16][SMP];
    int tid = threadIdx.x, lane = tid & 31, wid = tid >> 5;
    int wm = (wid & 1)*64, wn = (wid >> 1)*32;
    float c[4][4][4];
    #pragma unroll
    for (int i = 0; i < 4; i++) {
        #pragma unroll
        for (int j = 0; j < 4; j++) { c[i][j][0]=0.f; c[i][j][1]=0.f; c[i][j][2]=0.f; c[i][j][3]=0.f; }
    }
    int lr = tid >> 1, lc = (tid & 1)*8;   // A (weights) transpose loader
    int kr = tid >> 4, kc = (tid & 15)*8;  // B loader

    float4 w0 = *(const float4*)&Mb[(m0+lr)*PP + lc];
    float4 w1 = *(const float4*)&Mb[(m0+lr)*PP + lc + 4];
    float4 b0 = *(const float4*)&Y[(size_t)kr*NN + n0 + kc];
    float4 b1 = *(const float4*)&Y[(size_t)kr*NN + n0 + kc + 4];

    // phase 1: K=256 over Y with M
    for (int k0 = 0; k0 < PP; k0 += 16) {
        As[lc+0][lr]=f2tf(w0.x); As[lc+1][lr]=f2tf(w0.y); As[lc+2][lr]=f2tf(w0.z); As[lc+3][lr]=f2tf(w0.w);
        As[lc+4][lr]=f2tf(w1.x); As[lc+5][lr]=f2tf(w1.y); As[lc+6][lr]=f2tf(w1.z); As[lc+7][lr]=f2tf(w1.w);
        *(uint4*)&Bs[kr][kc]   = make_uint4(f2tf(b0.x),f2tf(b0.y),f2tf(b0.z),f2tf(b0.w));
        *(uint4*)&Bs[kr][kc+4] = make_uint4(f2tf(b1.x),f2tf(b1.y),f2tf(b1.z),f2tf(b1.w));
        __syncthreads();
        if (k0 + 16 < PP) {
            w0 = *(const float4*)&Mb[(m0+lr)*PP + k0+16 + lc];
            w1 = *(const float4*)&Mb[(m0+lr)*PP + k0+16 + lc + 4];
            b0 = *(const float4*)&Y[(size_t)(k0+16+kr)*NN + n0 + kc];
            b1 = *(const float4*)&Y[(size_t)(k0+16+kr)*NN + n0 + kc + 4];
        } else {
            w0 = *(const float4*)&g_WX[(m0+lr)*CC + lc];
            w1 = *(const float4*)&g_WX[(m0+lr)*CC + lc + 4];
            b0 = *(const float4*)&X[(size_t)kr*NN + n0 + kc];
            b1 = *(const float4*)&X[(size_t)kr*NN + n0 + kc + 4];
        }
        #pragma unroll
        for (int kk = 0; kk < 16; kk += 8) {
            unsigned ah[4][4], bh[4][2];
            int kb = kk + (lane & 3);
            int mb = wm + (lane >> 2);
            #pragma unroll
            for (int im = 0; im < 4; im++) {
                int m = mb + im*16;
                ah[im][0]=As[kb][m];   ah[im][1]=As[kb][m+8];
                ah[im][2]=As[kb+4][m]; ah[im][3]=As[kb+4][m+8];
            }
            int nb = wn + (lane >> 2);
            #pragma unroll
            for (int jn = 0; jn < 4; jn++) {
                int n = nb + jn*8;
                bh[jn][0]=Bs[kb][n]; bh[jn][1]=Bs[kb+4][n];
            }
            #pragma unroll
            for (int im = 0; im < 4; im++) {
                #pragma unroll
                for (int jn = 0; jn < 4; jn++) mma8(c[im][jn], ah[im], bh[jn]);
            }
        }
        __syncthreads();
    }
    // phase 2: K=512 over x with WX
    for (int k0 = 0; k0 < CC; k0 += 16) {
        As[lc+0][lr]=f2tf(w0.x); As[lc+1][lr]=f2tf(w0.y); As[lc+2][lr]=f2tf(w0.z); As[lc+3][lr]=f2tf(w0.w);
        As[lc+4][lr]=f2tf(w1.x); As[lc+5][lr]=f2tf(w1.y); As[lc+6][lr]=f2tf(w1.z); As[lc+7][lr]=f2tf(w1.w);
        *(uint4*)&Bs[kr][kc]   = make_uint4(f2tf(b0.x),f2tf(b0.y),f2tf(b0.z),f2tf(b0.w));
        *(uint4*)&Bs[kr][kc+4] = make_uint4(f2tf(b1.x),f2tf(b1.y),f2tf(b1.z),f2tf(b1.w));
        __syncthreads();
        if (k0 + 16 < CC) {
            w0 = *(const float4*)&g_WX[(m0+lr)*CC + k0+16 + lc];
            w1 = *(const float4*)&g_WX[(m0+lr)*CC + k0+16 + lc + 4];
            b0 = *(const float4*)&X[(size_t)(k0+16+kr)*NN + n0 + kc];
            b1 = *(const float4*)&X[(size_t)(k0+16+kr)*NN + n0 + kc + 4];
        }
        #pragma unroll
        for (int kk = 0; kk < 16; kk += 8) {
            unsigned ah[4][4], bh[4][2];
            int kb = kk + (lane & 3);
            int mb = wm + (lane >> 2);
            #pragma unroll
            for (int im = 0; im < 4; im++) {
                int m = mb + im*16;
                ah[im][0]=As[kb][m];   ah[im][1]=As[kb][m+8];
                ah[im][2]=As[kb+4][m]; ah[im][3]=As[kb+4][m+8];
            }
            int nb = wn + (lane >> 2);
            #pragma unroll
            for (int jn = 0; jn < 4; jn++) {
                int n = nb + jn*8;
                bh[jn][0]=Bs[kb][n]; bh[jn][1]=Bs[kb+4][n];
            }
            #pragma unroll
            for (int im = 0; im < 4; im++) {
                #pragma unroll
                for (int jn = 0; jn < 4; jn++) mma8(c[im][jn], ah[im], bh[jn]);
            }
        }
        __syncthreads();
    }
    #pragma unroll
    for (int im = 0; im < 4; im++) {
        int r0 = m0 + wm + im*16 + (lane >> 2);
        float c0 = g_ctot[r0], c1 = g_ctot[r0+8];
        #pragma unroll
        for (int jn = 0; jn < 4; jn++) {
            int col = n0 + wn + jn*8 + 2*(lane & 3);
            *(float2*)&Out[(size_t)r0*NN + col] =
                make_float2(fmaxf(c[im][jn][0]+c0, 0.f), fmaxf(c[im][jn][1]+c0, 0.f));
            *(float2*)&Out[(size_t)(r0+8)*NN + col] =
                make_float2(fmaxf(c[im][jn][2]+c1, 0.f), fmaxf(c[im][jn][3]+c1, 0.f));
        }
    }
}

// ---------------- launch -------------------------------------------------------
extern "C" void kernel_launch(void* const* d_in, const int* in_sizes, int n_in,
                              void* d_out, int out_size)
{
    (void)in_sizes; (void)n_in; (void)out_size;
    const float* x    = (const float*)d_in[0];
    const float* y    = (const float*)d_in[1];
    const float* wv   = (const float*)d_in[2];
    const float* bv   = (const float*)d_in[3];
    const float* wq   = (const float*)d_in[4];
    const float* bq   = (const float*)d_in[5];
    const float* w1d  = (const float*)d_in[6];
    const float* wo   = (const float*)d_in[11];
    const float* bo   = (const float*)d_in[12];
    const float* wx1  = (const float*)d_in[17];
    const float* bx1  = (const float*)d_in[18];
    const float* wx2  = (const float*)d_in[23];
    const float* bx2  = (const float*)d_in[24];
    float* out = (float*)d_out;

    fold_vectors<<<1, 256>>>(
        (const float*)d_in[7],  (const float*)d_in[8],  (const float*)d_in[9],  (const float*)d_in[10],
        (const float*)d_in[13], (const float*)d_in[14], (const float*)d_in[15], (const float*)d_in[16],
        (const float*)d_in[19], (const float*)d_in[20], (const float*)d_in[21], (const float*)d_in[22],
        (const float*)d_in[25], (const float*)d_in[26], (const float*)d_in[27], (const float*)d_in[28]);
    combine_w<<<256, 256>>>(wo, bo, w1d, wx2, bx2, wx1, bx1);
    convsx<<<BATCH*CC, 256>>>(x);
    uv_k<<<dim3(32, 8), 256>>>(wq, wv);
    gemm_G<<<dim3(4, 4, 8), 256>>>();
    gemm_T<<<dim3(4, 4, 8), 256>>>(wq);
    gemm_SA<<<dim3(16, 8), 256>>>(wv, bq, bv);
    gemm_M<<<dim3(4, 4, 8), 256>>>();
    gemm_final<<<dim3(32, 2, 8), 256>>>(x, y, out);
}

// round 12
// speedup vs baseline: 1.0702x; 1.0702x over previous
#include <cuda_runtime.h>
#include <cuda_bf16.h>
#include <math.h>

#define BATCH 8
#define PP 256
#define NN 4096
#define CC 512
#define EPSV 1e-5f
#define SMP 136   // smem row stride (words): 136 mod 32 == 8 -> conflict-free frag loads

// ---------------- scratch ------------------------------------------------------
__device__ unsigned g_Xh[BATCH*CC*NN/2];  // x as bf16 hi, packed 2/uint
__device__ unsigned g_Xl[BATCH*CC*NN/2];  // x residual lo
__device__ float g_G [BATCH*CC*CC];   // X X^T per batch
__device__ float g_T [BATCH*PP*CC];   // wq @ G
__device__ float g_S [BATCH*PP*PP];   // logits
__device__ float g_A [BATCH*PP*PP];   // softmax
__device__ float g_M [BATCH*PP*PP];   // Wc @ A^T
__device__ float g_Wc[PP*PP];
__device__ float g_WX[PP*CC];
__device__ float g_ctot[PP];
__device__ float g_sx[BATCH*CC];
__device__ float g_u [BATCH*PP];
__device__ float g_vv[BATCH*PP];
__device__ float g_s1[PP], g_t1[PP], g_so[PP], g_to[PP];
__device__ float g_sx1[PP], g_tx1[PP], g_sx2[PP], g_tx2[PP];

// ---------------- mma helpers --------------------------------------------------
__device__ __forceinline__ unsigned f2tf(float f) {
    unsigned u;
    asm("cvt.rna.tf32.f32 %0, %1;" : "=r"(u) : "f"(f));
    return u;
}
__device__ __forceinline__ void mma8(float c[4], const unsigned a[4], const unsigned b[2]) {
    asm volatile(
        "mma.sync.aligned.m16n8k8.row.col.f32.tf32.tf32.f32 "
        "{%0,%1,%2,%3},{%4,%5,%6,%7},{%8,%9},{%0,%1,%2,%3};\n"
        : "+f"(c[0]), "+f"(c[1]), "+f"(c[2]), "+f"(c[3])
        : "r"(a[0]), "r"(a[1]), "r"(a[2]), "r"(a[3]), "r"(b[0]), "r"(b[1]));
}
__device__ __forceinline__ void mmabf(float c[4], const unsigned a[4], const unsigned b[2]) {
    asm volatile(
        "mma.sync.aligned.m16n8k16.row.col.f32.bf16.bf16.f32 "
        "{%0,%1,%2,%3},{%4,%5,%6,%7},{%8,%9},{%0,%1,%2,%3};\n"
        : "+f"(c[0]), "+f"(c[1]), "+f"(c[2]), "+f"(c[3])
        : "r"(a[0]), "r"(a[1]), "r"(a[2]), "r"(a[3]), "r"(b[0]), "r"(b[1]));
}
__device__ __forceinline__ void pack2(float a, float b, unsigned& h, unsigned& l) {
    __nv_bfloat16 ha = __float2bfloat16(a), hb = __float2bfloat16(b);
    __nv_bfloat16 la = __float2bfloat16(a - __bfloat162float(ha));
    __nv_bfloat16 lb = __float2bfloat16(b - __bfloat162float(hb));
    h = ((unsigned)__bfloat16_as_ushort(hb) << 16) | __bfloat16_as_ushort(ha);
    l = ((unsigned)__bfloat16_as_ushort(lb) << 16) | __bfloat16_as_ushort(la);
}

// ---------------- BN fold ------------------------------------------------------
__global__ void fold_vectors(
    const float* __restrict__ g1,  const float* __restrict__ b1,
    const float* __restrict__ m1,  const float* __restrict__ v1,
    const float* __restrict__ go,  const float* __restrict__ bo_,
    const float* __restrict__ mo,  const float* __restrict__ vo,
    const float* __restrict__ gx1, const float* __restrict__ bx1_,
    const float* __restrict__ mx1, const float* __restrict__ vx1,
    const float* __restrict__ gx2, const float* __restrict__ bx2_,
    const float* __restrict__ mx2, const float* __restrict__ vx2)
{
    int p = threadIdx.x;
    float s;
    s = g1 [p]*rsqrtf(v1 [p]+EPSV); g_s1 [p]=s; g_t1 [p]=b1 [p]-m1 [p]*s;
    s = go [p]*rsqrtf(vo [p]+EPSV); g_so [p]=s; g_to [p]=bo_[p]-mo [p]*s;
    s = gx1[p]*rsqrtf(vx1[p]+EPSV); g_sx1[p]=s; g_tx1[p]=bx1_[p]-mx1[p]*s;
    s = gx2[p]*rsqrtf(vx2[p]+EPSV); g_sx2[p]=s; g_tx2[p]=bx2_[p]-mx2[p]*s;
}

// ---------------- combine linear chains ---------------------------------------
__global__ void combine_w(
    const float* __restrict__ wo,  const float* __restrict__ bo,
    const float* __restrict__ w1d,
    const float* __restrict__ wx2, const float* __restrict__ bx2,
    const float* __restrict__ wx1, const float* __restrict__ bx1)
{
    int o = blockIdx.x;
    int t = threadIdx.x;
    __shared__ float a1[PP], a2[PP], red[PP];
    float wo_k  = wo [o*PP + t];
    float wx2_k = wx2[o*PP + t];
    float so  = g_so[o], sx2 = g_sx2[o];
    a1[t] = wo_k  * g_s1 [t];
    a2[t] = wx2_k * g_sx1[t];
    red[t] = so * wo_k * g_t1[t]
           + sx2 * wx2_k * (g_sx1[t]*bx1[t] + g_tx1[t]);
    __syncthreads();
    for (int s = 128; s > 0; s >>= 1) {
        if (t < s) red[t] += red[t + s];
        __syncthreads();
    }
    if (t == 0)
        g_ctot[o] = red[0] + so*bo[o] + g_to[o] + sx2*bx2[o] + g_tx2[o];

    float s1sum = 0.f;
    #pragma unroll 8
    for (int k = 0; k < PP; k++) s1sum += a1[k] * w1d[k*PP + t];
    g_Wc[o*PP + t] = so * s1sum;

    float sA = 0.f, sB = 0.f;
    #pragma unroll 8
    for (int k = 0; k < PP; k++) {
        float w = a2[k];
        sA += w * wx1[k*CC + t];
        sB += w * wx1[k*CC + t + 256];
    }
    g_WX[o*CC + t]       = sx2 * sA;
    g_WX[o*CC + t + 256] = sx2 * sB;
}

// ---------------- fused: x -> bf16 hi/lo + row sums ----------------------------
__global__ __launch_bounds__(256) void convsx(const float* __restrict__ x)
{
    int row = blockIdx.x;                 // b*CC + c
    const float* src = x + (size_t)row*NN;
    unsigned* dh = g_Xh + (size_t)row*(NN/2);
    unsigned* dl = g_Xl + (size_t)row*(NN/2);
    int t = threadIdx.x;
    float s = 0.f;
    #pragma unroll
    for (int i = 0; i < 4; i++) {
        int e = t*4 + i*1024;             // coalesced float4
        float4 v = *(const float4*)&src[e];
        s += v.x + v.y + v.z + v.w;
        unsigned h01, l01, h23, l23;
        pack2(v.x, v.y, h01, l01);
        pack2(v.z, v.w, h23, l23);
        *(uint2*)&dh[e>>1] = make_uint2(h01, h23);
        *(uint2*)&dl[e>>1] = make_uint2(l01, l23);
    }
    __shared__ float wsum[8];
    #pragma unroll
    for (int o = 16; o > 0; o >>= 1) s += __shfl_xor_sync(0xffffffffu, s, o);
    if ((t & 31) == 0) wsum[t >> 5] = s;
    __syncthreads();
    if (t < 8) {
        float v = wsum[t];
        #pragma unroll
        for (int o = 4; o > 0; o >>= 1) v += __shfl_xor_sync(0xffu, v, o);
        if (t == 0) g_sx[row] = v;
    }
}

// ---------------- u = wq@sx, vv = wv@sx ----------------------------------------
__global__ void uv_k(const float* __restrict__ wq, const float* __restrict__ wv)
{
    int b = blockIdx.y;
    int w = threadIdx.x >> 5, lane = threadIdx.x & 31;
    int p = blockIdx.x * 8 + w;
    const float* sx = g_sx + b*CC;
    float su = 0.f, sv = 0.f;
    #pragma unroll
    for (int it = 0; it < 4; it++) {
        int c = lane*4 + it*128;
        float4 s4 = *(const float4*)&sx[c];
        float4 q4 = *(const float4*)&wq[p*CC + c];
        float4 v4 = *(const float4*)&wv[p*CC + c];
        su += q4.x*s4.x + q4.y*s4.y + q4.z*s4.z + q4.w*s4.w;
        sv += v4.x*s4.x + v4.y*s4.y + v4.z*s4.z + v4.w*s4.w;
    }
    #pragma unroll
    for (int o = 16; o > 0; o >>= 1) {
        su += __shfl_xor_sync(0xffffffffu, su, o);
        sv += __shfl_xor_sync(0xffffffffu, sv, o);
    }
    if (lane == 0) { g_u[b*PP + p] = su; g_vv[b*PP + p] = sv; }
}

// ---------------- G = X X^T  (bf16 2-split, 128x128, double-buffered) ----------
__global__ __launch_bounds__(256) void gemm_G()
{
    int batch = blockIdx.z;
    const unsigned* Xh = g_Xh + ((size_t)batch*CC*NN >> 1);
    const unsigned* Xl = g_Xl + ((size_t)batch*CC*NN >> 1);
    float* G = g_G + (size_t)batch*CC*CC;
    int m0 = blockIdx.y*128, n0 = blockIdx.x*128;
    __shared__ unsigned Ah_s[16][SMP], Al_s[16][SMP], Bh_s[16][SMP], Bl_s[16][SMP];
    int tid = threadIdx.x, lane = tid & 31, wid = tid >> 5;
    int wm = (wid & 1)*64, wn = (wid >> 1)*32;
    float c[4][4][4];
    #pragma unroll
    for (int i = 0; i < 4; i++) {
        #pragma unroll
        for (int j = 0; j < 4; j++) { c[i][j][0]=0.f; c[i][j][1]=0.f; c[i][j][2]=0.f; c[i][j][3]=0.f; }
    }

    int lr = tid >> 1, lc = (tid & 1)*8;
    const int NW = NN >> 1;
    const unsigned* pAh = &Xh[(size_t)(m0+lr)*NW + lc];
    const unsigned* pAl = &Xl[(size_t)(m0+lr)*NW + lc];
    const unsigned* pBh = &Xh[(size_t)(n0+lr)*NW + lc];
    const unsigned* pBl = &Xl[(size_t)(n0+lr)*NW + lc];

    uint4 ah0 = *(const uint4*)pAh, ah1 = *(const uint4*)(pAh+4);
    uint4 al0 = *(const uint4*)pAl, al1 = *(const uint4*)(pAl+4);
    uint4 bh0 = *(const uint4*)pBh, bh1 = *(const uint4*)(pBh+4);
    uint4 bl0 = *(const uint4*)pBl, bl1 = *(const uint4*)(pBl+4);

    for (int kp0 = 0; kp0 < NW; kp0 += 16) {
        Ah_s[lc+0][lr]=ah0.x; Ah_s[lc+1][lr]=ah0.y; Ah_s[lc+2][lr]=ah0.z; Ah_s[lc+3][lr]=ah0.w;
        Ah_s[lc+4][lr]=ah1.x; Ah_s[lc+5][lr]=ah1.y; Ah_s[lc+6][lr]=ah1.z; Ah_s[lc+7][lr]=ah1.w;
        Al_s[lc+0][lr]=al0.x; Al_s[lc+1][lr]=al0.y; Al_s[lc+2][lr]=al0.z; Al_s[lc+3][lr]=al0.w;
        Al_s[lc+4][lr]=al1.x; Al_s[lc+5][lr]=al1.y; Al_s[lc+6][lr]=al1.z; Al_s[lc+7][lr]=al1.w;
        Bh_s[lc+0][lr]=bh0.x; Bh_s[lc+1][lr]=bh0.y; Bh_s[lc+2][lr]=bh0.z; Bh_s[lc+3][lr]=bh0.w;
        Bh_s[lc+4][lr]=bh1.x; Bh_s[lc+5][lr]=bh1.y; Bh_s[lc+6][lr]=bh1.z; Bh_s[lc+7][lr]=bh1.w;
        Bl_s[lc+0][lr]=bl0.x; Bl_s[lc+1][lr]=bl0.y; Bl_s[lc+2][lr]=bl0.z; Bl_s[lc+3][lr]=bl0.w;
        Bl_s[lc+4][lr]=bl1.x; Bl_s[lc+5][lr]=bl1.y; Bl_s[lc+6][lr]=bl1.z; Bl_s[lc+7][lr]=bl1.w;
        __syncthreads();
        if (kp0 + 16 < NW) {
            ah0 = *(const uint4*)(pAh + kp0+16); ah1 = *(const uint4*)(pAh + kp0+20);
            al0 = *(const uint4*)(pAl + kp0+16); al1 = *(const uint4*)(pAl + kp0+20);
            bh0 = *(const uint4*)(pBh + kp0+16); bh1 = *(const uint4*)(pBh + kp0+20);
            bl0 = *(const uint4*)(pBl + kp0+16); bl1 = *(const uint4*)(pBl + kp0+20);
        }
        #pragma unroll
        for (int kk = 0; kk < 16; kk += 8) {
            unsigned ah[4][4], al[4][4], bh[4][2], bl[4][2];
            int kb = kk + (lane & 3);
            int mb = wm + (lane >> 2);
            #pragma unroll
            for (int im = 0; im < 4; im++) {
                int m = mb + im*16;
                ah[im][0]=Ah_s[kb][m];   ah[im][1]=Ah_s[kb][m+8];
                ah[im][2]=Ah_s[kb+4][m]; ah[im][3]=Ah_s[kb+4][m+8];
                al[im][0]=Al_s[kb][m];   al[im][1]=Al_s[kb][m+8];
                al[im][2]=Al_s[kb+4][m]; al[im][3]=Al_s[kb+4][m+8];
            }
            int nb = wn + (lane >> 2);
            #pragma unroll
            for (int jn = 0; jn < 4; jn++) {
                int n = nb + jn*8;
                bh[jn][0]=Bh_s[kb][n]; bh[jn][1]=Bh_s[kb+4][n];
                bl[jn][0]=Bl_s[kb][n]; bl[jn][1]=Bl_s[kb+4][n];
            }
            #pragma unroll
            for (int im = 0; im < 4; im++) {
                #pragma unroll
                for (int jn = 0; jn < 4; jn++) {
                    mmabf(c[im][jn], ah[im], bh[jn]);
                    mmabf(c[im][jn], al[im], bh[jn]);
                    mmabf(c[im][jn], ah[im], bl[jn]);
                }
            }
        }
        __syncthreads();
    }
    #pragma unroll
    for (int im = 0; im < 4; im++) {
        int r0 = m0 + wm + im*16 + (lane >> 2);
        #pragma unroll
        for (int jn = 0; jn < 4; jn++) {
            int col = n0 + wn + jn*8 + 2*(lane & 3);
            *(float2*)&G[(size_t)r0*CC + col]     = make_float2(c[im][jn][0], c[im][jn][1]);
            *(float2*)&G[(size_t)(r0+8)*CC + col] = make_float2(c[im][jn][2], c[im][jn][3]);
        }
    }
}

// ---------------- T = wq @ G  (fp32 SIMT, 64x128 tile, dbuf) -------------------
__global__ __launch_bounds__(256) void gemm_T(const float* __restrict__ wq)
{
    int batch = blockIdx.z;
    const float* Gm = g_G + (size_t)batch*CC*CC;
    float* Out = g_T + (size_t)batch*PP*CC;
    int m0 = blockIdx.y*64, n0 = blockIdx.x*128;
    __shared__ float Ws[16][65];
    __shared__ float Xs[16][128];
    int tid = threadIdx.x;
    int tm4 = (tid >> 4) * 4;
    int tn4 = (tid & 15) * 4;
    float acc[4][8];
    #pragma unroll
    for (int i = 0; i < 4; i++) {
        #pragma unroll
        for (int j = 0; j < 8; j++) acc[i][j] = 0.f;
    }
    int wr = tid >> 2, wc4 = (tid & 3) * 4;
    int xr = tid >> 4, xc = tid & 15;

    float4 w4 = *(const float4*)&wq[(m0+wr)*CC + wc4];
    const float4* Xr0 = (const float4*)&Gm[(size_t)xr*CC + n0];
    float4 x0 = Xr0[xc], x1 = Xr0[xc+16];

    for (int k0 = 0; k0 < CC; k0 += 16) {
        Ws[wc4+0][wr]=w4.x; Ws[wc4+1][wr]=w4.y; Ws[wc4+2][wr]=w4.z; Ws[wc4+3][wr]=w4.w;
        *(float4*)&Xs[xr][xc*4]    = x0;
        *(float4*)&Xs[xr][64+xc*4] = x1;
        __syncthreads();
        if (k0 + 16 < CC) {
            w4 = *(const float4*)&wq[(m0+wr)*CC + k0+16 + wc4];
            const float4* Xr = (const float4*)&Gm[(size_t)(k0+16+xr)*CC + n0];
            x0 = Xr[xc]; x1 = Xr[xc+16];
        }
        #pragma unroll
        for (int k = 0; k < 16; k++) {
            float a0=Ws[k][tm4+0], a1=Ws[k][tm4+1], a2=Ws[k][tm4+2], a3=Ws[k][tm4+3];
            float4 b0 = *(const float4*)&Xs[k][tn4];
            float4 b1 = *(const float4*)&Xs[k][tn4+64];
            acc[0][0]+=a0*b0.x; acc[0][1]+=a0*b0.y; acc[0][2]+=a0*b0.z; acc[0][3]+=a0*b0.w;
            acc[0][4]+=a0*b1.x; acc[0][5]+=a0*b1.y; acc[0][6]+=a0*b1.z; acc[0][7]+=a0*b1.w;
            acc[1][0]+=a1*b0.x; acc[1][1]+=a1*b0.y; acc[1][2]+=a1*b0.z; acc[1][3]+=a1*b0.w;
            acc[1][4]+=a1*b1.x; acc[1][5]+=a1*b1.y; acc[1][6]+=a1*b1.z; acc[1][7]+=a1*b1.w;
            acc[2][0]+=a2*b0.x; acc[2][1]+=a2*b0.y; acc[2][2]+=a2*b0.z; acc[2][3]+=a2*b0.w;
            acc[2][4]+=a2*b1.x; acc[2][5]+=a2*b1.y; acc[2][6]+=a2*b1.z; acc[2][7]+=a2*b1.w;
            acc[3][0]+=a3*b0.x; acc[3][1]+=a3*b0.y; acc[3][2]+=a3*b0.z; acc[3][3]+=a3*b0.w;
            acc[3][4]+=a3*b1.x; acc[3][5]+=a3*b1.y; acc[3][6]+=a3*b1.z; acc[3][7]+=a3*b1.w;
        }
        __syncthreads();
    }
    #pragma unroll
    for (int i = 0; i < 4; i++) {
        int row = m0 + tm4 + i;
        *(float4*)&Out[(size_t)row*CC + n0 + tn4]      = make_float4(acc[i][0],acc[i][1],acc[i][2],acc[i][3]);
        *(float4*)&Out[(size_t)row*CC + n0 + 64 + tn4] = make_float4(acc[i][4],acc[i][5],acc[i][6],acc[i][7]);
    }
}

// ---------------- S = T @ wv^T + rank-1 terms (fp32 NT SIMT) -------------------
__global__ __launch_bounds__(256) void gemm_Snt(const float* __restrict__ wv,
                                                const float* __restrict__ bq,
                                                const float* __restrict__ bv)
{
    int batch = blockIdx.z;
    const float* T = g_T + (size_t)batch*PP*CC;
    float* S = g_S + batch*PP*PP;
    int p0 = blockIdx.y*64, q0 = blockIdx.x*64;

    __shared__ float Qs[32][65];
    __shared__ float Vs[32][65];
    int tid = threadIdx.x;
    int tm4 = (tid >> 4) * 4;
    int tn4 = (tid & 15) * 4;
    float acc[4][4];
    #pragma unroll
    for (int i = 0; i < 4; i++) {
        #pragma unroll
        for (int j = 0; j < 4; j++) acc[i][j] = 0.f;
    }
    int r = tid >> 2, c8 = (tid & 3) * 8;

    for (int k0 = 0; k0 < CC; k0 += 32) {
        float4 qa = *(const float4*)&T[(size_t)(p0+r)*CC + k0 + c8];
        float4 qb = *(const float4*)&T[(size_t)(p0+r)*CC + k0 + c8 + 4];
        Qs[c8+0][r]=qa.x; Qs[c8+1][r]=qa.y; Qs[c8+2][r]=qa.z; Qs[c8+3][r]=qa.w;
        Qs[c8+4][r]=qb.x; Qs[c8+5][r]=qb.y; Qs[c8+6][r]=qb.z; Qs[c8+7][r]=qb.w;
        float4 va = *(const float4*)&wv[(size_t)(q0+r)*CC + k0 + c8];
        float4 vb = *(const float4*)&wv[(size_t)(q0+r)*CC + k0 + c8 + 4];
        Vs[c8+0][r]=va.x; Vs[c8+1][r]=va.y; Vs[c8+2][r]=va.z; Vs[c8+3][r]=va.w;
        Vs[c8+4][r]=vb.x; Vs[c8+5][r]=vb.y; Vs[c8+6][r]=vb.z; Vs[c8+7][r]=vb.w;
        __syncthreads();
        #pragma unroll
        for (int k = 0; k < 32; k++) {
            float a0=Qs[k][tm4+0], a1=Qs[k][tm4+1], a2=Qs[k][tm4+2], a3=Qs[k][tm4+3];
            float b0=Vs[k][tn4+0], b1=Vs[k][tn4+1], b2=Vs[k][tn4+2], b3=Vs[k][tn4+3];
            acc[0][0]+=a0*b0; acc[0][1]+=a0*b1; acc[0][2]+=a0*b2; acc[0][3]+=a0*b3;
            acc[1][0]+=a1*b0; acc[1][1]+=a1*b1; acc[1][2]+=a1*b2; acc[1][3]+=a1*b3;
            acc[2][0]+=a2*b0; acc[2][1]+=a2*b1; acc[2][2]+=a2*b2; acc[2][3]+=a2*b3;
            acc[3][0]+=a3*b0; acc[3][1]+=a3*b1; acc[3][2]+=a3*b2; acc[3][3]+=a3*b3;
        }
        __syncthreads();
    }
    const float* u  = g_u  + batch*PP;
    const float* vb2 = g_vv + batch*PP;
    #pragma unroll
    for (int i = 0; i < 4; i++) {
        int p = p0 + tm4 + i;
        float up = u[p], bqp = bq[p];
        float o[4];
        #pragma unroll
        for (int j = 0; j < 4; j++) {
            int q = q0 + tn4 + j;
            o[j] = acc[i][j] + up*bv[q] + bqp*(vb2[q] + 4096.f*bv[q]);
        }
        *(float4*)&S[p*PP + q0 + tn4] = make_float4(o[0], o[1], o[2], o[3]);
    }
}

// ---------------- softmax over q -----------------------------------------------
__global__ void softmax_k()
{
    int batch = blockIdx.y;
    int warp = threadIdx.x >> 5, lane = threadIdx.x & 31;
    int p = blockIdx.x * 8 + warp;
    const float* Srow = g_S + batch*PP*PP + p*PP;
    float v[8];
    float mx = -1e30f;
    #pragma unroll
    for (int i = 0; i < 8; i++) { v[i] = Srow[lane + 32*i]; mx = fmaxf(mx, v[i]); }
    #pragma unroll
    for (int o = 16; o > 0; o >>= 1) mx = fmaxf(mx, __shfl_xor_sync(0xffffffffu, mx, o));
    float sum = 0.f;
    #pragma unroll
    for (int i = 0; i < 8; i++) { v[i] = __expf(v[i] - mx); sum += v[i]; }
    #pragma unroll
    for (int o = 16; o > 0; o >>= 1) sum += __shfl_xor_sync(0xffffffffu, sum, o);
    float inv = 1.f / sum;
    float* Arow = g_A + batch*PP*PP + p*PP;
    #pragma unroll
    for (int i = 0; i < 8; i++) Arow[lane + 32*i] = v[i] * inv;
}

// ---------------- M = Wc @ A^T  (fp32 NT SIMT, 64x64 tiles, dbuf) --------------
__global__ __launch_bounds__(256) void gemm_M()
{
    int batch = blockIdx.z;
    const float* A = g_A + (size_t)batch*PP*PP;
    float* M = g_M + (size_t)batch*PP*PP;
    int o0 = blockIdx.y*64, p0 = blockIdx.x*64;

    __shared__ float Qs[32][65];   // Wc[k][o]
    __shared__ float Vs[32][65];   // A [k][p]
    int tid = threadIdx.x;
    int tm4 = (tid >> 4) * 4;
    int tn4 = (tid & 15) * 4;
    float acc[4][4];
    #pragma unroll
    for (int i = 0; i < 4; i++) {
        #pragma unroll
        for (int j = 0; j < 4; j++) acc[i][j] = 0.f;
    }
    int r = tid >> 2, c8 = (tid & 3) * 8;

    float4 qa = *(const float4*)&g_Wc[(o0+r)*PP + c8];
    float4 qb = *(const float4*)&g_Wc[(o0+r)*PP + c8 + 4];
    float4 va = *(const float4*)&A[(size_t)(p0+r)*PP + c8];
    float4 vb = *(const float4*)&A[(size_t)(p0+r)*PP + c8 + 4];

    for (int k0 = 0; k0 < PP; k0 += 32) {
        Qs[c8+0][r]=qa.x; Qs[c8+1][r]=qa.y; Qs[c8+2][r]=qa.z; Qs[c8+3][r]=qa.w;
        Qs[c8+4][r]=qb.x; Qs[c8+5][r]=qb.y; Qs[c8+6][r]=qb.z; Qs[c8+7][r]=qb.w;
        Vs[c8+0][r]=va.x; Vs[c8+1][r]=va.y; Vs[c8+2][r]=va.z; Vs[c8+3][r]=va.w;
        Vs[c8+4][r]=vb.x; Vs[c8+5][r]=vb.y; Vs[c8+6][r]=vb.z; Vs[c8+7][r]=vb.w;
        __syncthreads();
        if (k0 + 32 < PP) {
            qa = *(const float4*)&g_Wc[(o0+r)*PP + k0+32 + c8];
            qb = *(const float4*)&g_Wc[(o0+r)*PP + k0+32 + c8 + 4];
            va = *(const float4*)&A[(size_t)(p0+r)*PP + k0+32 + c8];
            vb = *(const float4*)&A[(size_t)(p0+r)*PP + k0+32 + c8 + 4];
        }
        #pragma unroll
        for (int k = 0; k < 32; k++) {
            float a0=Qs[k][tm4+0], a1=Qs[k][tm4+1], a2=Qs[k][tm4+2], a3=Qs[k][tm4+3];
            float b0=Vs[k][tn4+0], b1=Vs[k][tn4+1], b2=Vs[k][tn4+2], b3=Vs[k][tn4+3];
            acc[0][0]+=a0*b0; acc[0][1]+=a0*b1; acc[0][2]+=a0*b2; acc[0][3]+=a0*b3;
            acc[1][0]+=a1*b0; acc[1][1]+=a1*b1; acc[1][2]+=a1*b2; acc[1][3]+=a1*b3;
            acc[2][0]+=a2*b0; acc[2][1]+=a2*b1; acc[2][2]+=a2*b2; acc[2][3]+=a2*b3;
            acc[3][0]+=a3*b0; acc[3][1]+=a3*b1; acc[3][2]+=a3*b2; acc[3][3]+=a3*b3;
        }
        __syncthreads();
    }
    #pragma unroll
    for (int i = 0; i < 4; i++) {
        *(float4*)&M[(o0+tm4+i)*PP + p0 + tn4] =
            make_float4(acc[i][0], acc[i][1], acc[i][2], acc[i][3]);
    }
}

// ---------------- final: out = relu(M@Y + WX@x + ctot) (1x tf32, dbuf) ---------
__global__ __launch_bounds__(256) void gemm_final(const float* __restrict__ x,
                                                  const float* __restrict__ y,
                                                  float* __restrict__ out)
{
    int batch = blockIdx.z;
    const float* Mb = g_M + (size_t)batch*PP*PP;
    const float* Y  = y + (size_t)batch*PP*NN;
    const float* X  = x + (size_t)batch*CC*NN;
    float* Out = out + (size_t)batch*PP*NN;
    int m0 = blockIdx.y*128, n0 = blockIdx.x*128;
    __shared__ unsigned As[16][SMP], Bs[16][SMP];
    int tid = threadIdx.x, lane = tid & 31, wid = tid >> 5;
    int wm = (wid & 1)*64, wn = (wid >> 1)*32;
    float c[4][4][4];
    #pragma unroll
    for (int i = 0; i < 4; i++) {
        #pragma unroll
        for (int j = 0; j < 4; j++) { c[i][j][0]=0.f; c[i][j][1]=0.f; c[i][j][2]=0.f; c[i][j][3]=0.f; }
    }
    int lr = tid >> 1, lc = (tid & 1)*8;   // A (weights) transpose loader
    int kr = tid >> 4, kc = (tid & 15)*8;  // B loader

    float4 w0 = *(const float4*)&Mb[(m0+lr)*PP + lc];
    float4 w1 = *(const float4*)&Mb[(m0+lr)*PP + lc + 4];
    float4 b0 = *(const float4*)&Y[(size_t)kr*NN + n0 + kc];
    float4 b1 = *(const float4*)&Y[(size_t)kr*NN + n0 + kc + 4];

    // phase 1: K=256 over Y with M
    for (int k0 = 0; k0 < PP; k0 += 16) {
        As[lc+0][lr]=f2tf(w0.x); As[lc+1][lr]=f2tf(w0.y); As[lc+2][lr]=f2tf(w0.z); As[lc+3][lr]=f2tf(w0.w);
        As[lc+4][lr]=f2tf(w1.x); As[lc+5][lr]=f2tf(w1.y); As[lc+6][lr]=f2tf(w1.z); As[lc+7][lr]=f2tf(w1.w);
        *(uint4*)&Bs[kr][kc]   = make_uint4(f2tf(b0.x),f2tf(b0.y),f2tf(b0.z),f2tf(b0.w));
        *(uint4*)&Bs[kr][kc+4] = make_uint4(f2tf(b1.x),f2tf(b1.y),f2tf(b1.z),f2tf(b1.w));
        __syncthreads();
        if (k0 + 16 < PP) {
            w0 = *(const float4*)&Mb[(m0+lr)*PP + k0+16 + lc];
            w1 = *(const float4*)&Mb[(m0+lr)*PP + k0+16 + lc + 4];
            b0 = *(const float4*)&Y[(size_t)(k0+16+kr)*NN + n0 + kc];
            b1 = *(const float4*)&Y[(size_t)(k0+16+kr)*NN + n0 + kc + 4];
        } else {
            w0 = *(const float4*)&g_WX[(m0+lr)*CC + lc];
            w1 = *(const float4*)&g_WX[(m0+lr)*CC + lc + 4];
            b0 = *(const float4*)&X[(size_t)kr*NN + n0 + kc];
            b1 = *(const float4*)&X[(size_t)kr*NN + n0 + kc + 4];
        }
        #pragma unroll
        for (int kk = 0; kk < 16; kk += 8) {
            unsigned ah[4][4], bh[4][2];
            int kb = kk + (lane & 3);
            int mb = wm + (lane >> 2);
            #pragma unroll
            for (int im = 0; im < 4; im++) {
                int m = mb + im*16;
                ah[im][0]=As[kb][m];   ah[im][1]=As[kb][m+8];
                ah[im][2]=As[kb+4][m]; ah[im][3]=As[kb+4][m+8];
            }
            int nb = wn + (lane >> 2);
            #pragma unroll
            for (int jn = 0; jn < 4; jn++) {
                int n = nb + jn*8;
                bh[jn][0]=Bs[kb][n]; bh[jn][1]=Bs[kb+4][n];
            }
            #pragma unroll
            for (int im = 0; im < 4; im++) {
                #pragma unroll
                for (int jn = 0; jn < 4; jn++) mma8(c[im][jn], ah[im], bh[jn]);
            }
        }
        __syncthreads();
    }
    // phase 2: K=512 over x with WX
    for (int k0 = 0; k0 < CC; k0 += 16) {
        As[lc+0][lr]=f2tf(w0.x); As[lc+1][lr]=f2tf(w0.y); As[lc+2][lr]=f2tf(w0.z); As[lc+3][lr]=f2tf(w0.w);
        As[lc+4][lr]=f2tf(w1.x); As[lc+5][lr]=f2tf(w1.y); As[lc+6][lr]=f2tf(w1.z); As[lc+7][lr]=f2tf(w1.w);
        *(uint4*)&Bs[kr][kc]   = make_uint4(f2tf(b0.x),f2tf(b0.y),f2tf(b0.z),f2tf(b0.w));
        *(uint4*)&Bs[kr][kc+4] = make_uint4(f2tf(b1.x),f2tf(b1.y),f2tf(b1.z),f2tf(b1.w));
        __syncthreads();
        if (k0 + 16 < CC) {
            w0 = *(const float4*)&g_WX[(m0+lr)*CC + k0+16 + lc];
            w1 = *(const float4*)&g_WX[(m0+lr)*CC + k0+16 + lc + 4];
            b0 = *(const float4*)&X[(size_t)(k0+16+kr)*NN + n0 + kc];
            b1 = *(const float4*)&X[(size_t)(k0+16+kr)*NN + n0 + kc + 4];
        }
        #pragma unroll
        for (int kk = 0; kk < 16; kk += 8) {
            unsigned ah[4][4], bh[4][2];
            int kb = kk + (lane & 3);
            int mb = wm + (lane >> 2);
            #pragma unroll
            for (int im = 0; im < 4; im++) {
                int m = mb + im*16;
                ah[im][0]=As[kb][m];   ah[im][1]=As[kb][m+8];
                ah[im][2]=As[kb+4][m]; ah[im][3]=As[kb+4][m+8];
            }
            int nb = wn + (lane >> 2);
            #pragma unroll
            for (int jn = 0; jn < 4; jn++) {
                int n = nb + jn*8;
                bh[jn][0]=Bs[kb][n]; bh[jn][1]=Bs[kb+4][n];
            }
            #pragma unroll
            for (int im = 0; im < 4; im++) {
                #pragma unroll
                for (int jn = 0; jn < 4; jn++) mma8(c[im][jn], ah[im], bh[jn]);
            }
        }
        __syncthreads();
    }
    #pragma unroll
    for (int im = 0; im < 4; im++) {
        int r0 = m0 + wm + im*16 + (lane >> 2);
        float c0 = g_ctot[r0], c1 = g_ctot[r0+8];
        #pragma unroll
        for (int jn = 0; jn < 4; jn++) {
            int col = n0 + wn + jn*8 + 2*(lane & 3);
            *(float2*)&Out[(size_t)r0*NN + col] =
                make_float2(fmaxf(c[im][jn][0]+c0, 0.f), fmaxf(c[im][jn][1]+c0, 0.f));
            *(float2*)&Out[(size_t)(r0+8)*NN + col] =
                make_float2(fmaxf(c[im][jn][2]+c1, 0.f), fmaxf(c[im][jn][3]+c1, 0.f));
        }
    }
}

// ---------------- launch -------------------------------------------------------
extern "C" void kernel_launch(void* const* d_in, const int* in_sizes, int n_in,
                              void* d_out, int out_size)
{
    (void)in_sizes; (void)n_in; (void)out_size;
    const float* x    = (const float*)d_in[0];
    const float* y    = (const float*)d_in[1];
    const float* wv   = (const float*)d_in[2];
    const float* bv   = (const float*)d_in[3];
    const float* wq   = (const float*)d_in[4];
    const float* bq   = (const float*)d_in[5];
    const float* w1d  = (const float*)d_in[6];
    const float* wo   = (const float*)d_in[11];
    const float* bo   = (const float*)d_in[12];
    const float* wx1  = (const float*)d_in[17];
    const float* bx1  = (const float*)d_in[18];
    const float* wx2  = (const float*)d_in[23];
    const float* bx2  = (const float*)d_in[24];
    float* out = (float*)d_out;

    fold_vectors<<<1, 256>>>(
        (const float*)d_in[7],  (const float*)d_in[8],  (const float*)d_in[9],  (const float*)d_in[10],
        (const float*)d_in[13], (const float*)d_in[14], (const float*)d_in[15], (const float*)d_in[16],
        (const float*)d_in[19], (const float*)d_in[20], (const float*)d_in[21], (const float*)d_in[22],
        (const float*)d_in[25], (const float*)d_in[26], (const float*)d_in[27], (const float*)d_in[28]);
    combine_w<<<256, 256>>>(wo, bo, w1d, wx2, bx2, wx1, bx1);
    convsx<<<BATCH*CC, 256>>>(x);
    uv_k<<<dim3(32, 8), 256>>>(wq, wv);
    gemm_G<<<dim3(4, 4, 8), 256>>>();
    gemm_T<<<dim3(4, 4, 8), 256>>>(wq);
    gemm_Snt<<<dim3(4, 4, 8), 256>>>(wv, bq, bv);
    softmax_k<<<dim3(32, 8), 256>>>();
    gemm_M<<<dim3(4, 4, 8), 256>>>();
    gemm_final<<<dim3(32, 2, 8), 256>>>(x, y, out);
}